// round 6
// baseline (speedup 1.0000x reference)
#include <cuda_runtime.h>
#include <math.h>
#include <stdint.h>

// Problem constants
#define B_  64
#define T_  1024
#define C_  256
#define BR  64              // query rows per CTA
#define BC  64              // key rows per tile
#define XS  260             // x-tile smem row stride (floats)
#define PS  68              // P/S smem row stride (floats)
#define NTILE (T_ / BR)     // 16

// Device scratch (allocation-free rule)
__device__ float g_xtf[B_ * T_ * C_];        // tf32-rounded copy of x
__device__ float g_cs16[B_ * 16 * C_];       // colsum partials
__device__ float g_colsum[B_ * C_];          // per-batch column sums (fp32 exact)
__device__ float g_rownrm[B_ * T_];          // per-row L2 norm of tf32(x)
__device__ float g_knmax[B_];                // max norm over valid (masked-in) keys
__device__ float g_part[B_ * NTILE * C_];    // per (b,qtile) LN column partials

// ---------------------------------------------------------------------------
static __device__ __forceinline__ uint32_t smem_u32(const void* p) {
    return (uint32_t)__cvta_generic_to_shared(p);
}
static __device__ __forceinline__ void cp16(uint32_t dst, const void* src) {
    asm volatile("cp.async.cg.shared.global [%0], [%1], 16;" :: "r"(dst), "l"(src));
}
static __device__ __forceinline__ uint32_t f2tf32(float v) {
    uint32_t u;
    asm("cvt.rna.tf32.f32 %0, %1;" : "=r"(u) : "f"(v));
    return u;
}
static __device__ __forceinline__ void mma_tf32(
    float& d0, float& d1, float& d2, float& d3,
    uint32_t a0, uint32_t a1, uint32_t a2, uint32_t a3,
    uint32_t b0, uint32_t b1)
{
    asm volatile(
        "mma.sync.aligned.m16n8k8.row.col.f32.tf32.tf32.f32 "
        "{%0,%1,%2,%3},{%4,%5,%6,%7},{%8,%9},{%0,%1,%2,%3};"
        : "+f"(d0), "+f"(d1), "+f"(d2), "+f"(d3)
        : "r"(a0), "r"(a1), "r"(a2), "r"(a3), "r"(b0), "r"(b1));
}
static __device__ __forceinline__ uint32_t ldsf(const float* p) {
    return __float_as_uint(*p);
}

// ---------------------------------------------------------------------------
// Kernel 1: round x -> tf32 copy + colsum partials + per-row norms of tf32(x)
// grid (B_, 16), 256 threads; CTA covers 64 rows
// ---------------------------------------------------------------------------
__global__ void prep_kernel(const float* __restrict__ x) {
    const int b = blockIdx.x, ch = blockIdx.y, c = threadIdx.x;
    const size_t base = ((size_t)b * T_ + (size_t)ch * 64) * C_ + c;
    const float* xp = x + base;
    float* op = g_xtf + base;
    float s = 0.f;
#pragma unroll 8
    for (int t = 0; t < 64; t++) {
        float v = xp[(size_t)t * C_];
        s += v;
        op[(size_t)t * C_] = __uint_as_float(f2tf32(v));
    }
    g_cs16[(b * 16 + ch) * C_ + c] = s;

    // per-row L2 norms on tf32-rounded values (4 threads per row)
    const int r = threadIdx.x >> 2, part = threadIdx.x & 3;
    const float* rp = x + ((size_t)b * T_ + (size_t)ch * 64 + r) * C_ + part * 64;
    float n2 = 0.f;
#pragma unroll 8
    for (int cc = 0; cc < 64; cc++) {
        float v = __uint_as_float(f2tf32(rp[cc]));
        n2 += v * v;
    }
    n2 += __shfl_xor_sync(0xffffffffu, n2, 1);
    n2 += __shfl_xor_sync(0xffffffffu, n2, 2);
    if (part == 0) g_rownrm[b * T_ + ch * 64 + r] = sqrtf(n2);
}

// Kernel 1b: reduce colsums + compute per-batch max valid-key norm
__global__ void reduce_kernel(const int* __restrict__ km) {
    __shared__ float red[256];
    const int b = blockIdx.x, c = threadIdx.x;
    float s = 0.f;
#pragma unroll
    for (int i = 0; i < 16; i++) s += g_cs16[(b * 16 + i) * C_ + c];
    g_colsum[b * C_ + c] = s;

    float mx = 0.f;
#pragma unroll
    for (int i = 0; i < 4; i++) {
        int t = c + i * 256;
        float n = g_rownrm[b * T_ + t];
        mx = fmaxf(mx, km[b * T_ + t] ? n : 0.f);
    }
    red[c] = mx;
    __syncthreads();
#pragma unroll
    for (int off = 128; off > 0; off >>= 1) {
        if (c < off) red[c] = fmaxf(red[c], red[c + off]);
        __syncthreads();
    }
    if (c == 0) g_knmax[b] = red[0];
}

// ---------------------------------------------------------------------------
// Kernel 2: flash attention, tf32 mma, FIXED-BOUND softmax (no online max),
// fused LN + column partials. One CTA per (qtile, batch). 256 threads.
// ---------------------------------------------------------------------------
__global__ void __launch_bounds__(256, 1)
attn_kernel(const int* __restrict__ km, const float* __restrict__ gamma,
            const float* __restrict__ beta)
{
    extern __shared__ float smf[];
    float* Qs = smf;                         // [64][XS]
    float* Xb0 = Qs + BR * XS;               // [64][XS] double-buffered K(=V) tile
    float* Xb1 = Xb0 + BC * XS;
    float* Ps  = Xb1 + BC * XS;              // [64][PS] probabilities (tf32)
    float* mb_s = Ps + BR * PS;              // [BR] per-row exp bound
    float* lp_s = mb_s + BR;                 // [BR][2] l partials (per wn)
    float* l_s  = lp_s + 2 * BR;             // [BR] final denominators
    float* mu_s = l_s + BR;
    float* rs_s = mu_s + BR;

    const int qt   = 15 - blockIdx.x;        // heavy tiles first
    const int b    = blockIdx.y;
    const int tid  = threadIdx.x;
    const int lane = tid & 31;
    const int w    = tid >> 5;
    const int wm   = w >> 1;                 // 0..3
    const int wn   = w & 1;                  // 0..1
    const int jj   = lane & 3;
    const int g8   = lane >> 2;
    const int q0   = qt * BR;
    const int r0   = wm * 16 + g8;           // fragment row; second row r0+8
    const float* xb = g_xtf + (size_t)b * T_ * C_;

    // Prefetch Q tile + key tile 0
#pragma unroll
    for (int it = 0; it < 16; it++) {
        int idx = tid + it * 256;
        int r = idx >> 6, c = (idx & 63) << 2;
        cp16(smem_u32(Qs + r * XS + c), xb + (size_t)(q0 + r) * C_ + c);
    }
#pragma unroll
    for (int it = 0; it < 16; it++) {
        int idx = tid + it * 256;
        int r = idx >> 6, c = (idx & 63) << 2;
        cp16(smem_u32(Xb0 + r * XS + c), xb + (size_t)r * C_ + c);
    }
    asm volatile("cp.async.commit_group;");

    // per-row exp bound: m_b = ||q_r|| * max_valid||k|| / 16 (+ margin)
    if (tid < BR) {
        float nb = g_rownrm[b * T_ + q0 + tid] * g_knmax[b];
        mb_s[tid] = nb * 0.0625f * 1.0002f + 1e-6f;
    }
    __syncthreads();
    const float mb0 = mb_s[r0], mb1 = mb_s[r0 + 8];

    float Oacc[16][4];
#pragma unroll
    for (int nt = 0; nt < 16; nt++)
#pragma unroll
        for (int e = 0; e < 4; e++) Oacc[nt][e] = 0.f;
    float lsum0 = 0.f, lsum1 = 0.f;          // denominator partials (rows r0, r0+8)

    for (int st = 0; st <= qt; st++) {
        float* Xc = (st & 1) ? Xb1 : Xb0;
        asm volatile("cp.async.wait_group 0;");
        __syncthreads();   // tile ready; prev iter done with buffers & Ps

        if (st < qt) {     // prefetch next key tile
            float* Xn = (st & 1) ? Xb0 : Xb1;
            const float* src = xb + (size_t)(st + 1) * BC * C_;
#pragma unroll
            for (int it = 0; it < 16; it++) {
                int idx = tid + it * 256;
                int r = idx >> 6, c = (idx & 63) << 2;
                cp16(smem_u32(Xn + r * XS + c), src + (size_t)r * C_ + c);
            }
            asm volatile("cp.async.commit_group;");
        }

        const int s0 = st * BC;

        // key-padding mask for my 8 S-columns
        int kmr[4][2];
#pragma unroll
        for (int nt = 0; nt < 4; nt++)
#pragma unroll
            for (int e = 0; e < 2; e++)
                kmr[nt][e] = km[b * T_ + s0 + wn * 32 + nt * 8 + 2 * jj + e];

        // ---- Stage A: S = Q K^T (tf32 mma) ----
        float sacc[4][4];
#pragma unroll
        for (int nt = 0; nt < 4; nt++)
#pragma unroll
            for (int e = 0; e < 4; e++) sacc[nt][e] = 0.f;

#pragma unroll 4
        for (int k0 = 0; k0 < C_; k0 += 8) {
            uint32_t a0 = ldsf(Qs + r0 * XS + k0 + jj);
            uint32_t a1 = ldsf(Qs + (r0 + 8) * XS + k0 + jj);
            uint32_t a2 = ldsf(Qs + r0 * XS + k0 + 4 + jj);
            uint32_t a3 = ldsf(Qs + (r0 + 8) * XS + k0 + 4 + jj);
#pragma unroll
            for (int nt = 0; nt < 4; nt++) {
                const float* bp = Xc + (wn * 32 + nt * 8 + g8) * XS + k0;
                uint32_t b0 = ldsf(bp + jj);
                uint32_t b1 = ldsf(bp + 4 + jj);
                mma_tf32(sacc[nt][0], sacc[nt][1], sacc[nt][2], sacc[nt][3],
                         a0, a1, a2, a3, b0, b1);
            }
        }

        // ---- Fused fixed-bound softmax numerators: p = exp(s/16 - m_b) ----
#pragma unroll
        for (int nt = 0; nt < 4; nt++) {
            int scb = wn * 32 + nt * 8 + 2 * jj;
            bool c00 = ((s0 + scb)     <= (q0 + r0))     && kmr[nt][0];
            bool c01 = ((s0 + scb + 1) <= (q0 + r0))     && kmr[nt][1];
            bool c10 = ((s0 + scb)     <= (q0 + r0 + 8)) && kmr[nt][0];
            bool c11 = ((s0 + scb + 1) <= (q0 + r0 + 8)) && kmr[nt][1];
            float p00 = c00 ? __expf(sacc[nt][0] * 0.0625f - mb0) : 0.f;
            float p01 = c01 ? __expf(sacc[nt][1] * 0.0625f - mb0) : 0.f;
            float p10 = c10 ? __expf(sacc[nt][2] * 0.0625f - mb1) : 0.f;
            float p11 = c11 ? __expf(sacc[nt][3] * 0.0625f - mb1) : 0.f;
            lsum0 += p00 + p01;
            lsum1 += p10 + p11;
            *(float2*)(Ps + r0 * PS + scb) =
                make_float2(__uint_as_float(f2tf32(p00)), __uint_as_float(f2tf32(p01)));
            *(float2*)(Ps + (r0 + 8) * PS + scb) =
                make_float2(__uint_as_float(f2tf32(p10)), __uint_as_float(f2tf32(p11)));
        }
        __syncthreads();

        // ---- Stage B: O += P @ X (no rescale needed) ----
#pragma unroll 2
        for (int s8 = 0; s8 < BC; s8 += 8) {
            uint32_t pa0 = ldsf(Ps + r0 * PS + s8 + jj);
            uint32_t pa1 = ldsf(Ps + (r0 + 8) * PS + s8 + jj);
            uint32_t pa2 = ldsf(Ps + r0 * PS + s8 + 4 + jj);
            uint32_t pa3 = ldsf(Ps + (r0 + 8) * PS + s8 + 4 + jj);
#pragma unroll
            for (int nt = 0; nt < 16; nt++) {
                const int cn = wn * 128 + nt * 8 + g8;
                uint32_t b0 = ldsf(Xc + (s8 + jj) * XS + cn);
                uint32_t b1 = ldsf(Xc + (s8 + 4 + jj) * XS + cn);
                mma_tf32(Oacc[nt][0], Oacc[nt][1], Oacc[nt][2], Oacc[nt][3],
                         pa0, pa1, pa2, pa3, b0, b1);
            }
        }
    }

    // ---- Reduce l: shuffle over jj lanes, then deterministic 2-way combine ----
    lsum0 += __shfl_xor_sync(0xffffffffu, lsum0, 1);
    lsum0 += __shfl_xor_sync(0xffffffffu, lsum0, 2);
    lsum1 += __shfl_xor_sync(0xffffffffu, lsum1, 1);
    lsum1 += __shfl_xor_sync(0xffffffffu, lsum1, 2);
    if (jj == 0) {
        lp_s[r0 * 2 + wn]       = lsum0;
        lp_s[(r0 + 8) * 2 + wn] = lsum1;
    }
    __syncthreads();
    if (tid < BR) l_s[tid] = lp_s[tid * 2] + lp_s[tid * 2 + 1];
    __syncthreads();

    // ---- Epilogue: normalize / degenerate fixup, stash O in Xb0 ----
    float* Os = Xb0;
    {
        const float lv0 = l_s[r0], lv1 = l_s[r0 + 8];
        const bool d0 = (lv0 == 0.f), d1 = (lv1 == 0.f);
        const float inv0 = d0 ? 0.f : (1.f / lv0);
        const float inv1 = d1 ? 0.f : (1.f / lv1);
#pragma unroll
        for (int nt = 0; nt < 16; nt++)
#pragma unroll
            for (int e = 0; e < 2; e++) {
                const int c = wn * 128 + nt * 8 + 2 * jj + e;
                const float cm = g_colsum[b * C_ + c] * (1.f / 1024.f);
                Os[r0 * XS + c]       = d0 ? cm : Oacc[nt][e] * inv0;
                Os[(r0 + 8) * XS + c] = d1 ? cm : Oacc[nt][2 + e] * inv1;
            }
    }
    __syncthreads();

    // ---- LayerNorm stats (4 threads per row, two-pass) ----
    {
        const int r = tid >> 2, part = tid & 3;
        const float* row = Os + r * XS + part * 64;
        float s1 = 0.f;
#pragma unroll 8
        for (int c = 0; c < 64; c++) s1 += row[c];
        s1 += __shfl_xor_sync(0xffffffffu, s1, 1);
        s1 += __shfl_xor_sync(0xffffffffu, s1, 2);
        const float mu = s1 * (1.f / 256.f);
        float s2 = 0.f;
#pragma unroll 8
        for (int c = 0; c < 64; c++) { float d = row[c] - mu; s2 += d * d; }
        s2 += __shfl_xor_sync(0xffffffffu, s2, 1);
        s2 += __shfl_xor_sync(0xffffffffu, s2, 2);
        const float rstd = rsqrtf(s2 * (1.f / 256.f) + 1e-9f);
        if (part == 0) { mu_s[r] = mu; rs_s[r] = rstd; }
    }
    __syncthreads();

    // ---- Column partials over this q-tile's 64 rows ----
    {
        float acc = 0.f;
#pragma unroll 4
        for (int r = 0; r < BR; r++)
            acc += (Os[r * XS + tid] - mu_s[r]) * rs_s[r];
        g_part[(b * NTILE + qt) * C_ + tid] = gamma[tid] * acc + 64.f * beta[tid];
    }
}

// ---------------------------------------------------------------------------
// Kernel 3: reduce q-tile partials -> mean over T
// ---------------------------------------------------------------------------
__global__ void finalize_kernel(float* __restrict__ out) {
    const int b = blockIdx.x, c = threadIdx.x;
    float s = 0.f;
#pragma unroll
    for (int qt = 0; qt < NTILE; qt++) s += g_part[(b * NTILE + qt) * C_ + c];
    out[b * C_ + c] = s * (1.f / 1024.f);
}

// ---------------------------------------------------------------------------
extern "C" void kernel_launch(void* const* d_in, const int* in_sizes, int n_in,
                              void* d_out, int out_size)
{
    const float* x     = (const float*)d_in[0];
    const int*   km    = (const int*)  d_in[1];
    const float* gamma = (const float*)d_in[2];
    const float* beta  = (const float*)d_in[3];
    float*       out   = (float*)d_out;

    const size_t smem_bytes =
        (size_t)(BR * XS + 2 * BC * XS + BR * PS + 6 * BR) * sizeof(float);
    cudaFuncSetAttribute(attn_kernel,
                         cudaFuncAttributeMaxDynamicSharedMemorySize,
                         (int)smem_bytes);

    prep_kernel<<<dim3(B_, 16), 256>>>(x);
    reduce_kernel<<<B_, 256>>>(km);
    attn_kernel<<<dim3(NTILE, B_), 256, smem_bytes>>>(km, gamma, beta);
    finalize_kernel<<<B_, 256>>>(out);
}

// round 8
// speedup vs baseline: 2.1742x; 2.1742x over previous
#include <cuda_runtime.h>
#include <cuda_fp16.h>
#include <math.h>
#include <stdint.h>

// Problem constants
#define B_  64
#define T_  1024
#define C_  256
#define BR  64               // query rows per CTA
#define BC  64               // key rows per tile
#define NTILE (T_ / BR)      // 16
#define OSS 260              // final O staging stride (floats)

// SMEM byte offsets (per CTA, ~86 KB -> 2 CTAs/SM)
#define OF_Q   0             // 64 rows x 528B (264 halves, odd 16B-granule stride)
#define OF_X   33792         // 64 rows x 528B
#define OF_S   67584         // 64 rows x 272B: fp32 scores, overlaid fp16 P
#define OF_MS  84992         // m[64]
#define OF_LS  85248         // l[64]
#define OF_AS  85504         // alpha[64]
#define OF_MU  85760         // mu[64]
#define OF_RS  86016         // rstd[64]
#define SMEM_TOTAL 86272

// Device scratch
__device__ __half g_xh[B_ * T_ * C_];     // fp16 copy of x
__device__ float  g_cs16[B_ * 16 * C_];   // colsum partials (exact fp32)
__device__ float  g_colsum[B_ * C_];
__device__ float  g_part[B_ * NTILE * C_];

// ---------------------------------------------------------------------------
static __device__ __forceinline__ uint32_t smem_u32(const void* p) {
    return (uint32_t)__cvta_generic_to_shared(p);
}
static __device__ __forceinline__ void cp16(uint32_t dst, const void* src) {
    asm volatile("cp.async.cg.shared.global [%0], [%1], 16;" :: "r"(dst), "l"(src));
}
static __device__ __forceinline__ void ldsm4(
    uint32_t& r0, uint32_t& r1, uint32_t& r2, uint32_t& r3, uint32_t a)
{
    asm volatile("ldmatrix.sync.aligned.m8n8.x4.shared.b16 {%0,%1,%2,%3}, [%4];"
                 : "=r"(r0), "=r"(r1), "=r"(r2), "=r"(r3) : "r"(a));
}
static __device__ __forceinline__ void ldsm4t(
    uint32_t& r0, uint32_t& r1, uint32_t& r2, uint32_t& r3, uint32_t a)
{
    asm volatile("ldmatrix.sync.aligned.m8n8.x4.trans.shared.b16 {%0,%1,%2,%3}, [%4];"
                 : "=r"(r0), "=r"(r1), "=r"(r2), "=r"(r3) : "r"(a));
}
static __device__ __forceinline__ void mma_f16(
    float* d, uint32_t a0, uint32_t a1, uint32_t a2, uint32_t a3,
    uint32_t b0, uint32_t b1)
{
    asm volatile(
        "mma.sync.aligned.m16n8k16.row.col.f32.f16.f16.f32 "
        "{%0,%1,%2,%3},{%4,%5,%6,%7},{%8,%9},{%0,%1,%2,%3};"
        : "+f"(d[0]), "+f"(d[1]), "+f"(d[2]), "+f"(d[3])
        : "r"(a0), "r"(a1), "r"(a2), "r"(a3), "r"(b0), "r"(b1));
}

// ---------------------------------------------------------------------------
// Kernel 1: fp16 copy of x + exact fp32 colsum partials
// ---------------------------------------------------------------------------
__global__ void prep_kernel(const float* __restrict__ x) {
    const int b = blockIdx.x, ch = blockIdx.y, c = threadIdx.x;
    const size_t base = ((size_t)b * T_ + (size_t)ch * 64) * C_ + c;
    const float* xp = x + base;
    __half* op = g_xh + base;
    float s = 0.f;
#pragma unroll 8
    for (int t = 0; t < 64; t++) {
        float v = xp[(size_t)t * C_];
        s += v;
        op[(size_t)t * C_] = __float2half_rn(v);
    }
    g_cs16[(b * 16 + ch) * C_ + c] = s;
}

__global__ void colsum_reduce_kernel() {
    const int b = blockIdx.x, c = threadIdx.x;
    float s = 0.f;
#pragma unroll
    for (int i = 0; i < 16; i++) s += g_cs16[(b * 16 + i) * C_ + c];
    g_colsum[b * C_ + c] = s;
}

// ---------------------------------------------------------------------------
// Kernel 2: flash attention, fp16 mma.sync + ldmatrix, online softmax,
// fused LN + column partials. One CTA per (qtile, batch). 256 thr, 2 CTAs/SM.
// ---------------------------------------------------------------------------
__global__ void __launch_bounds__(256, 2)
attn_kernel(const int* __restrict__ km, const float* __restrict__ gamma,
            const float* __restrict__ beta)
{
    extern __shared__ char smc[];
    float* smf = (float*)smc;
    const uint32_t sb = smem_u32(smc);

    const int qt   = 15 - blockIdx.x;        // heavy tiles first
    const int b    = blockIdx.y;
    const int tid  = threadIdx.x;
    const int lane = tid & 31;
    const int w    = tid >> 5;
    const int wm   = w >> 1;                 // 0..3 (M strips of 16)
    const int wn   = w & 1;                  // 0..1 (N halves)
    const int jj   = lane & 3;
    const int g8   = lane >> 2;
    const int l15  = lane & 15;
    const int lh   = lane >> 4;              // 0/1
    const int q0   = qt * BR;
    const int r0   = wm * 16 + g8;           // C-frag row; second row r0+8
    const __half* xb = g_xh + (size_t)b * T_ * C_;

    // ldmatrix lane base addresses
    // A (Q) x4: rows wm*16 + l15, +16B for k8-15 half
    const uint32_t aQ = sb + OF_Q + (uint32_t)(wm * 16 + l15) * 528 + lh * 16;
    // B (K) x4 non-trans: lanes 0-7 n0-7@k0, 8-15 n0-7@k8, 16-23 n8-15@k0, 24-31 n8-15@k8
    const uint32_t aK = sb + OF_X + (uint32_t)(wn * 32 + (lane & 7) + lh * 8) * 528
                        + ((lane >> 3) & 1) * 16;
    // A (P) x4: rows wm*16+l15 in the S/P buffer (stride 272B)
    const uint32_t aP = sb + OF_S + (uint32_t)(wm * 16 + l15) * 272 + lh * 16;
    // B (X) x4 trans: rows key l15, col block offset (wn*128 halves) + 16B per lh
    const uint32_t aX = sb + OF_X + (uint32_t)l15 * 528 + (uint32_t)wn * 256 + lh * 16;

    // Prefetch Q tile (64 rows x 32 granules)
#pragma unroll
    for (int it = 0; it < 8; it++) {
        int idx = tid + it * 256;
        int r = idx >> 5, g = idx & 31;
        cp16(sb + OF_Q + r * 528 + g * 16, xb + (size_t)(q0 + r) * C_ + g * 8);
    }
    asm volatile("cp.async.commit_group;");

    if (tid < BR) { smf[OF_MS / 4 + tid] = -INFINITY; smf[OF_LS / 4 + tid] = 0.f; }

    float Oacc[16][4];
#pragma unroll
    for (int nt = 0; nt < 16; nt++)
#pragma unroll
        for (int e = 0; e < 4; e++) Oacc[nt][e] = 0.f;

    for (int st = 0; st <= qt; st++) {
        const int s0 = st * BC;
        __syncthreads();                       // prev stage B done with X & P

        // Load X(=K=V) tile st
#pragma unroll
        for (int it = 0; it < 8; it++) {
            int idx = tid + it * 256;
            int r = idx >> 5, g = idx & 31;
            cp16(sb + OF_X + r * 528 + g * 16, xb + (size_t)(s0 + r) * C_ + g * 8);
        }
        asm volatile("cp.async.commit_group;");

        // key-padding mask for my 8 S-columns (overlaps the cp.async)
        int kmr[4][2];
#pragma unroll
        for (int nt = 0; nt < 4; nt++)
#pragma unroll
            for (int e = 0; e < 2; e++)
                kmr[nt][e] = km[b * T_ + s0 + wn * 32 + nt * 8 + 2 * jj + e];

        asm volatile("cp.async.wait_group 0;");
        __syncthreads();                       // X visible to all threads

        // ---- Stage A: S = Q K^T (fp16 mma, warp tile 16x32) ----
        float sacc[4][4];
#pragma unroll
        for (int nt = 0; nt < 4; nt++)
#pragma unroll
            for (int e = 0; e < 4; e++) sacc[nt][e] = 0.f;

#pragma unroll
        for (int k = 0; k < 16; k++) {         // k16 steps over C=256
            uint32_t a0, a1, a2, a3, b0, b1, b2, b3, c0, c1, c2, c3;
            ldsm4(a0, a1, a2, a3, aQ + k * 32);
            ldsm4(b0, b1, b2, b3, aK + k * 32);            // n0-15
            ldsm4(c0, c1, c2, c3, aK + 16 * 528 + k * 32); // n16-31
            mma_f16(sacc[0], a0, a1, a2, a3, b0, b1);
            mma_f16(sacc[1], a0, a1, a2, a3, b2, b3);
            mma_f16(sacc[2], a0, a1, a2, a3, c0, c1);
            mma_f16(sacc[3], a0, a1, a2, a3, c2, c3);
        }

        // Store masked, scaled fp32 scores to S
#pragma unroll
        for (int nt = 0; nt < 4; nt++) {
            int scb = wn * 32 + nt * 8 + 2 * jj;
            float* srow0 = (float*)(smc + OF_S + r0 * 272);
            float* srow1 = (float*)(smc + OF_S + (r0 + 8) * 272);
            float v00 = (((s0 + scb)     <= (q0 + r0))     && kmr[nt][0]) ? sacc[nt][0] * 0.0625f : -INFINITY;
            float v01 = (((s0 + scb + 1) <= (q0 + r0))     && kmr[nt][1]) ? sacc[nt][1] * 0.0625f : -INFINITY;
            float v10 = (((s0 + scb)     <= (q0 + r0 + 8)) && kmr[nt][0]) ? sacc[nt][2] * 0.0625f : -INFINITY;
            float v11 = (((s0 + scb + 1) <= (q0 + r0 + 8)) && kmr[nt][1]) ? sacc[nt][3] * 0.0625f : -INFINITY;
            *(float2*)(srow0 + scb) = make_float2(v00, v01);
            *(float2*)(srow1 + scb) = make_float2(v10, v11);
        }
        __syncthreads();

        // ---- Online softmax (branchless): warp w owns rows 8w..8w+7 ----
        {
            const int row = w * 8 + g8;
            float* rp = (float*)(smc + OF_S + row * 272);
            __half* hp = (__half*)(smc + OF_S + row * 272);   // P overlays S
            float vv[16];
            float mt = -INFINITY;
#pragma unroll
            for (int i = 0; i < 16; i++) { vv[i] = rp[jj + 4 * i]; mt = fmaxf(mt, vv[i]); }
            mt = fmaxf(mt, __shfl_xor_sync(0xffffffffu, mt, 1));
            mt = fmaxf(mt, __shfl_xor_sync(0xffffffffu, mt, 2));
            const float mo = smf[OF_MS / 4 + row];
            const float mn = fmaxf(mo, mt);
            const float alpha = (mo == -INFINITY) ? 0.f : __expf(mo - mn);
            float p[16], sum = 0.f;
#pragma unroll
            for (int i = 0; i < 16; i++) {
                p[i] = (vv[i] == -INFINITY) ? 0.f : __expf(vv[i] - mn);
                sum += p[i];
            }
            sum += __shfl_xor_sync(0xffffffffu, sum, 1);
            sum += __shfl_xor_sync(0xffffffffu, sum, 2);
            __syncwarp();                       // all S reads done before P overwrite
#pragma unroll
            for (int i = 0; i < 16; i++) hp[jj + 4 * i] = __float2half_rn(p[i]);
            if (jj == 0) {
                smf[OF_MS / 4 + row] = mn;
                smf[OF_LS / 4 + row] = smf[OF_LS / 4 + row] * alpha + sum;
                smf[OF_AS / 4 + row] = alpha;
            }
        }
        __syncthreads();

        // ---- Stage B: O = alpha*O + P @ X (fp16 mma, warp tile 16x128) ----
        {
            const float al0 = smf[OF_AS / 4 + r0], al1 = smf[OF_AS / 4 + r0 + 8];
#pragma unroll
            for (int nt = 0; nt < 16; nt++) {
                Oacc[nt][0] *= al0; Oacc[nt][1] *= al0;
                Oacc[nt][2] *= al1; Oacc[nt][3] *= al1;
            }
#pragma unroll
            for (int ks = 0; ks < 4; ks++) {    // k16 steps over 64 keys
                uint32_t pa0, pa1, pa2, pa3;
                ldsm4(pa0, pa1, pa2, pa3, aP + ks * 32);
#pragma unroll
                for (int pr = 0; pr < 8; pr++) {
                    uint32_t x0, x1, x2, x3;
                    ldsm4t(x0, x1, x2, x3, aX + ks * 16 * 528 + pr * 32);
                    mma_f16(Oacc[2 * pr],     pa0, pa1, pa2, pa3, x0, x1);
                    mma_f16(Oacc[2 * pr + 1], pa0, pa1, pa2, pa3, x2, x3);
                }
            }
        }
    }

    // ---- Epilogue: normalize / degenerate fixup, stash O over Q/X region ----
    __syncthreads();                            // all done with Q/X/P
    float* Os = smf;                            // stride OSS floats, base 0
    {
        const float lv0 = smf[OF_LS / 4 + r0], lv1 = smf[OF_LS / 4 + r0 + 8];
        const bool d0 = (lv0 == 0.f), d1 = (lv1 == 0.f);
        const float inv0 = d0 ? 0.f : (1.f / lv0);
        const float inv1 = d1 ? 0.f : (1.f / lv1);
#pragma unroll
        for (int nt = 0; nt < 16; nt++)
#pragma unroll
            for (int e = 0; e < 2; e++) {
                const int c = wn * 128 + nt * 8 + 2 * jj + e;
                const float cm = g_colsum[b * C_ + c] * (1.f / 1024.f);
                Os[r0 * OSS + c]       = d0 ? cm : Oacc[nt][e] * inv0;
                Os[(r0 + 8) * OSS + c] = d1 ? cm : Oacc[nt][2 + e] * inv1;
            }
    }
    __syncthreads();

    // ---- LayerNorm stats (4 threads per row, two-pass) ----
    {
        const int r = tid >> 2, part = tid & 3;
        const float* row = Os + r * OSS + part * 64;
        float s1 = 0.f;
#pragma unroll 8
        for (int c = 0; c < 64; c++) s1 += row[c];
        s1 += __shfl_xor_sync(0xffffffffu, s1, 1);
        s1 += __shfl_xor_sync(0xffffffffu, s1, 2);
        const float mu = s1 * (1.f / 256.f);
        float s2 = 0.f;
#pragma unroll 8
        for (int c = 0; c < 64; c++) { float d = row[c] - mu; s2 += d * d; }
        s2 += __shfl_xor_sync(0xffffffffu, s2, 1);
        s2 += __shfl_xor_sync(0xffffffffu, s2, 2);
        const float rstd = rsqrtf(s2 * (1.f / 256.f) + 1e-9f);
        if (part == 0) { smf[OF_MU / 4 + r] = mu; smf[OF_RS / 4 + r] = rstd; }
    }
    __syncthreads();

    // ---- Column partials over this q-tile's 64 rows ----
    {
        float acc = 0.f;
#pragma unroll 4
        for (int r = 0; r < BR; r++)
            acc += (Os[r * OSS + tid] - smf[OF_MU / 4 + r]) * smf[OF_RS / 4 + r];
        g_part[(b * NTILE + qt) * C_ + tid] = gamma[tid] * acc + 64.f * beta[tid];
    }
}

// ---------------------------------------------------------------------------
// Kernel 3: reduce q-tile partials -> mean over T
// ---------------------------------------------------------------------------
__global__ void finalize_kernel(float* __restrict__ out) {
    const int b = blockIdx.x, c = threadIdx.x;
    float s = 0.f;
#pragma unroll
    for (int qtl = 0; qtl < NTILE; qtl++) s += g_part[(b * NTILE + qtl) * C_ + c];
    out[b * C_ + c] = s * (1.f / 1024.f);
}

// ---------------------------------------------------------------------------
extern "C" void kernel_launch(void* const* d_in, const int* in_sizes, int n_in,
                              void* d_out, int out_size)
{
    const float* x     = (const float*)d_in[0];
    const int*   km    = (const int*)  d_in[1];
    const float* gamma = (const float*)d_in[2];
    const float* beta  = (const float*)d_in[3];
    float*       out   = (float*)d_out;

    cudaFuncSetAttribute(attn_kernel,
                         cudaFuncAttributeMaxDynamicSharedMemorySize, SMEM_TOTAL);

    prep_kernel<<<dim3(B_, 16), 256>>>(x);
    colsum_reduce_kernel<<<B_, 256>>>();
    attn_kernel<<<dim3(NTILE, B_), 256, SMEM_TOTAL>>>(km, gamma, beta);
    finalize_kernel<<<B_, 256>>>(out);
}

// round 9
// speedup vs baseline: 2.6940x; 1.2391x over previous
#include <cuda_runtime.h>
#include <cuda_fp16.h>
#include <math.h>
#include <stdint.h>

// Problem constants
#define B_  64
#define T_  1024
#define C_  256
#define BR  64               // query rows per CTA (= key tile)
#define NTILE (T_ / BR)      // 16
#define OSS 260              // final O staging stride (floats)

// SMEM byte offsets (per CTA ~99.5 KB -> 2 CTAs/SM)
#define OF_Q   0             // 64 rows x 528B
#define OF_X0  33792         // 64 rows x 528B (double-buffered K=V tile)
#define OF_X1  67584
#define OF_MU  101376        // mu[64]
#define OF_RS  101632        // rstd[64]
#define SMEM_TOTAL 101888

// Device scratch
__device__ __half g_xh[B_ * T_ * C_];
__device__ float  g_cs16[B_ * 16 * C_];
__device__ float  g_colsum[B_ * C_];
__device__ float  g_part[B_ * NTILE * C_];

// ---------------------------------------------------------------------------
static __device__ __forceinline__ uint32_t smem_u32(const void* p) {
    return (uint32_t)__cvta_generic_to_shared(p);
}
static __device__ __forceinline__ void cp16(uint32_t dst, const void* src) {
    asm volatile("cp.async.cg.shared.global [%0], [%1], 16;" :: "r"(dst), "l"(src));
}
static __device__ __forceinline__ void ldsm4(
    uint32_t& r0, uint32_t& r1, uint32_t& r2, uint32_t& r3, uint32_t a)
{
    asm volatile("ldmatrix.sync.aligned.m8n8.x4.shared.b16 {%0,%1,%2,%3}, [%4];"
                 : "=r"(r0), "=r"(r1), "=r"(r2), "=r"(r3) : "r"(a));
}
static __device__ __forceinline__ void ldsm4t(
    uint32_t& r0, uint32_t& r1, uint32_t& r2, uint32_t& r3, uint32_t a)
{
    asm volatile("ldmatrix.sync.aligned.m8n8.x4.trans.shared.b16 {%0,%1,%2,%3}, [%4];"
                 : "=r"(r0), "=r"(r1), "=r"(r2), "=r"(r3) : "r"(a));
}
static __device__ __forceinline__ void mma_f16(
    float* d, uint32_t a0, uint32_t a1, uint32_t a2, uint32_t a3,
    uint32_t b0, uint32_t b1)
{
    asm volatile(
        "mma.sync.aligned.m16n8k16.row.col.f32.f16.f16.f32 "
        "{%0,%1,%2,%3},{%4,%5,%6,%7},{%8,%9},{%0,%1,%2,%3};"
        : "+f"(d[0]), "+f"(d[1]), "+f"(d[2]), "+f"(d[3])
        : "r"(a0), "r"(a1), "r"(a2), "r"(a3), "r"(b0), "r"(b1));
}
static __device__ __forceinline__ uint32_t packh2(float x, float y) {
    __half2 h = __floats2half2_rn(x, y);
    return *(uint32_t*)&h;
}

// ---------------------------------------------------------------------------
// Kernel 1: fp16 copy of x + exact fp32 colsum partials
// ---------------------------------------------------------------------------
__global__ void prep_kernel(const float* __restrict__ x) {
    const int b = blockIdx.x, ch = blockIdx.y, c = threadIdx.x;
    const size_t base = ((size_t)b * T_ + (size_t)ch * 64) * C_ + c;
    const float* xp = x + base;
    __half* op = g_xh + base;
    float s = 0.f;
#pragma unroll 8
    for (int t = 0; t < 64; t++) {
        float v = xp[(size_t)t * C_];
        s += v;
        op[(size_t)t * C_] = __float2half_rn(v);
    }
    g_cs16[(b * 16 + ch) * C_ + c] = s;
}

__global__ void colsum_reduce_kernel() {
    const int b = blockIdx.x, c = threadIdx.x;
    float s = 0.f;
#pragma unroll
    for (int i = 0; i < 16; i++) s += g_cs16[(b * 16 + i) * C_ + c];
    g_colsum[b * C_ + c] = s;
}

// ---------------------------------------------------------------------------
// Kernel 2: flash attention, fp16 mma, register-resident P + in-register
// online softmax (zero smem, zero syncs in softmax). 128 thr, 2 CTAs/SM.
// Warp w owns q rows 16w..16w+15 x ALL 64 keys.
// ---------------------------------------------------------------------------
__global__ void __launch_bounds__(128, 2)
attn_kernel(const int* __restrict__ km, const float* __restrict__ gamma,
            const float* __restrict__ beta)
{
    extern __shared__ char smc[];
    float* smf = (float*)smc;
    const uint32_t sb = smem_u32(smc);

    const int qt   = 15 - blockIdx.x;        // heavy tiles first
    const int b    = blockIdx.y;
    const int tid  = threadIdx.x;
    const int lane = tid & 31;
    const int w    = tid >> 5;
    const int jj   = lane & 3;
    const int g8   = lane >> 2;
    const int l15  = lane & 15;
    const int lh   = lane >> 4;
    const int q0   = qt * BR;
    const int row0 = w * 16 + g8;            // local q row (second: +8)
    const int grow0 = q0 + row0, grow1 = grow0 + 8;
    const __half* xb = g_xh + (size_t)b * T_ * C_;

    const uint32_t aQ = sb + OF_Q + (uint32_t)(w * 16 + l15) * 528 + lh * 16;

    // Prefetch Q + X tile 0 (one group)
#pragma unroll
    for (int it = 0; it < 16; it++) {
        int idx = tid + it * 128;
        int r = idx >> 5, g = idx & 31;
        cp16(sb + OF_Q + r * 528 + g * 16, xb + (size_t)(q0 + r) * C_ + g * 8);
    }
#pragma unroll
    for (int it = 0; it < 16; it++) {
        int idx = tid + it * 128;
        int r = idx >> 5, g = idx & 31;
        cp16(sb + OF_X0 + r * 528 + g * 16, xb + (size_t)r * C_ + g * 8);
    }
    asm volatile("cp.async.commit_group;");

    float Oacc[32][4];
#pragma unroll
    for (int i = 0; i < 32; i++)
#pragma unroll
        for (int e = 0; e < 4; e++) Oacc[i][e] = 0.f;
    float m0 = -INFINITY, m1 = -INFINITY, l0 = 0.f, l1 = 0.f;

    for (int st = 0; st <= qt; st++) {
        const uint32_t Xoff = (st & 1) ? OF_X1 : OF_X0;
        const int s0 = st * BR;

        asm volatile("cp.async.wait_group 0;");
        __syncthreads();                      // X[st] visible; X[(st+1)&1] free

        if (st < qt) {                        // prefetch next tile
            const uint32_t Xn = ((st + 1) & 1) ? OF_X1 : OF_X0;
            const __half* src = xb + (size_t)(st + 1) * BR * C_;
#pragma unroll
            for (int it = 0; it < 16; it++) {
                int idx = tid + it * 128;
                int r = idx >> 5, g = idx & 31;
                cp16(sb + Xn + r * 528 + g * 16, src + (size_t)r * C_ + g * 8);
            }
            asm volatile("cp.async.commit_group;");
        }

        // key-padding mask pairs for my 16 columns
        int2 kmv[8];
#pragma unroll
        for (int nt = 0; nt < 8; nt++)
            kmv[nt] = *(const int2*)(km + b * T_ + s0 + nt * 8 + 2 * jj);

        // ---- Stage A: S = Q K^T, warp tile 16x64 ----
        uint32_t aK[4];
#pragma unroll
        for (int nb = 0; nb < 4; nb++)
            aK[nb] = sb + Xoff + (uint32_t)(nb * 16 + (lane & 7) + lh * 8) * 528
                     + ((lane >> 3) & 1) * 16;

        float sacc[8][4];
#pragma unroll
        for (int nt = 0; nt < 8; nt++)
#pragma unroll
            for (int e = 0; e < 4; e++) sacc[nt][e] = 0.f;

#pragma unroll
        for (int k = 0; k < 16; k++) {
            uint32_t a0, a1, a2, a3;
            ldsm4(a0, a1, a2, a3, aQ + k * 32);
#pragma unroll
            for (int nb = 0; nb < 4; nb++) {
                uint32_t b0, b1, b2, b3;
                ldsm4(b0, b1, b2, b3, aK[nb] + k * 32);
                mma_f16(sacc[2 * nb],     a0, a1, a2, a3, b0, b1);
                mma_f16(sacc[2 * nb + 1], a0, a1, a2, a3, b2, b3);
            }
        }

        // ---- Mask + in-register online softmax (quad shuffles only) ----
#pragma unroll
        for (int nt = 0; nt < 8; nt++) {
#pragma unroll
            for (int e = 0; e < 2; e++) {
                int key = s0 + nt * 8 + 2 * jj + e;
                int ok = e ? kmv[nt].y : kmv[nt].x;
                sacc[nt][e]     = ((key <= grow0) && ok) ? sacc[nt][e] * 0.0625f     : -INFINITY;
                sacc[nt][2 + e] = ((key <= grow1) && ok) ? sacc[nt][2 + e] * 0.0625f : -INFINITY;
            }
        }
        float mt0 = -INFINITY, mt1 = -INFINITY;
#pragma unroll
        for (int nt = 0; nt < 8; nt++) {
            mt0 = fmaxf(mt0, fmaxf(sacc[nt][0], sacc[nt][1]));
            mt1 = fmaxf(mt1, fmaxf(sacc[nt][2], sacc[nt][3]));
        }
        mt0 = fmaxf(mt0, __shfl_xor_sync(0xffffffffu, mt0, 1));
        mt0 = fmaxf(mt0, __shfl_xor_sync(0xffffffffu, mt0, 2));
        mt1 = fmaxf(mt1, __shfl_xor_sync(0xffffffffu, mt1, 1));
        mt1 = fmaxf(mt1, __shfl_xor_sync(0xffffffffu, mt1, 2));
        const float mn0 = fmaxf(m0, mt0), mn1 = fmaxf(m1, mt1);
        const float al0 = (m0 == -INFINITY) ? 0.f : __expf(m0 - mn0);
        const float al1 = (m1 == -INFINITY) ? 0.f : __expf(m1 - mn1);

        float p0[8][2], p1[8][2], sum0 = 0.f, sum1 = 0.f;
#pragma unroll
        for (int nt = 0; nt < 8; nt++) {
#pragma unroll
            for (int e = 0; e < 2; e++) {
                float a = sacc[nt][e],     pa = (a == -INFINITY) ? 0.f : __expf(a - mn0);
                float c = sacc[nt][2 + e], pc = (c == -INFINITY) ? 0.f : __expf(c - mn1);
                p0[nt][e] = pa; sum0 += pa;
                p1[nt][e] = pc; sum1 += pc;
            }
        }
        sum0 += __shfl_xor_sync(0xffffffffu, sum0, 1);
        sum0 += __shfl_xor_sync(0xffffffffu, sum0, 2);
        sum1 += __shfl_xor_sync(0xffffffffu, sum1, 1);
        sum1 += __shfl_xor_sync(0xffffffffu, sum1, 2);
        l0 = l0 * al0 + sum0;  m0 = mn0;
        l1 = l1 * al1 + sum1;  m1 = mn1;

        // rescale O accumulators
#pragma unroll
        for (int i = 0; i < 32; i++) {
            Oacc[i][0] *= al0; Oacc[i][1] *= al0;
            Oacc[i][2] *= al1; Oacc[i][3] *= al1;
        }

        // pack P into A-fragments (C-frag layout == A-frag layout)
        uint32_t pA[4][4];
#pragma unroll
        for (int kb = 0; kb < 4; kb++) {
            pA[kb][0] = packh2(p0[2 * kb][0],     p0[2 * kb][1]);
            pA[kb][1] = packh2(p1[2 * kb][0],     p1[2 * kb][1]);
            pA[kb][2] = packh2(p0[2 * kb + 1][0], p0[2 * kb + 1][1]);
            pA[kb][3] = packh2(p1[2 * kb + 1][0], p1[2 * kb + 1][1]);
        }

        // ---- Stage B: O += P @ X, warp tile 16x256 ----
        const uint32_t aXb = sb + Xoff + (uint32_t)l15 * 528 + lh * 16;
#pragma unroll
        for (int ks = 0; ks < 4; ks++) {
#pragma unroll
            for (int n16 = 0; n16 < 16; n16++) {
                uint32_t x0, x1, x2, x3;
                ldsm4t(x0, x1, x2, x3, aXb + ks * 16 * 528 + n16 * 32);
                mma_f16(Oacc[2 * n16],     pA[ks][0], pA[ks][1], pA[ks][2], pA[ks][3], x0, x1);
                mma_f16(Oacc[2 * n16 + 1], pA[ks][0], pA[ks][1], pA[ks][2], pA[ks][3], x2, x3);
            }
        }
    }

    // ---- Epilogue: normalize / degenerate fixup -> Os staging ----
    __syncthreads();                           // all compute done; reuse Q/X0 smem
    float* Os = smf;
    {
        const bool d0 = (l0 == 0.f), d1 = (l1 == 0.f);
        const float inv0 = d0 ? 0.f : (1.f / l0);
        const float inv1 = d1 ? 0.f : (1.f / l1);
#pragma unroll
        for (int nt2 = 0; nt2 < 32; nt2++)
#pragma unroll
            for (int e = 0; e < 2; e++) {
                const int c = nt2 * 8 + 2 * jj + e;
                const float cm = g_colsum[b * C_ + c] * (1.f / 1024.f);
                Os[row0 * OSS + c]       = d0 ? cm : Oacc[nt2][e] * inv0;
                Os[(row0 + 8) * OSS + c] = d1 ? cm : Oacc[nt2][2 + e] * inv1;
            }
    }
    __syncthreads();

    // ---- LayerNorm stats (2 threads per row) ----
    {
        const int r = tid >> 1, hf = tid & 1;
        const float* row = Os + r * OSS + hf * 128;
        float s1 = 0.f;
#pragma unroll 8
        for (int c = 0; c < 128; c++) s1 += row[c];
        s1 += __shfl_xor_sync(0xffffffffu, s1, 1);
        const float mu = s1 * (1.f / 256.f);
        float s2 = 0.f;
#pragma unroll 8
        for (int c = 0; c < 128; c++) { float d = row[c] - mu; s2 += d * d; }
        s2 += __shfl_xor_sync(0xffffffffu, s2, 1);
        const float rstd = rsqrtf(s2 * (1.f / 256.f) + 1e-9f);
        if (hf == 0) { smf[OF_MU / 4 + r] = mu; smf[OF_RS / 4 + r] = rstd; }
    }
    __syncthreads();

    // ---- Column partials (each thread: cols tid, tid+128) ----
    {
        float acc0 = 0.f, acc1 = 0.f;
#pragma unroll 4
        for (int r = 0; r < BR; r++) {
            const float muv = smf[OF_MU / 4 + r], rsv = smf[OF_RS / 4 + r];
            acc0 += (Os[r * OSS + tid]       - muv) * rsv;
            acc1 += (Os[r * OSS + tid + 128] - muv) * rsv;
        }
        float* gp = g_part + (size_t)(b * NTILE + qt) * C_;
        gp[tid]       = gamma[tid]       * acc0 + 64.f * beta[tid];
        gp[tid + 128] = gamma[tid + 128] * acc1 + 64.f * beta[tid + 128];
    }
}

// ---------------------------------------------------------------------------
// Kernel 3: reduce q-tile partials -> mean over T
// ---------------------------------------------------------------------------
__global__ void finalize_kernel(float* __restrict__ out) {
    const int b = blockIdx.x, c = threadIdx.x;
    float s = 0.f;
#pragma unroll
    for (int qtl = 0; qtl < NTILE; qtl++) s += g_part[(b * NTILE + qtl) * C_ + c];
    out[b * C_ + c] = s * (1.f / 1024.f);
}

// ---------------------------------------------------------------------------
extern "C" void kernel_launch(void* const* d_in, const int* in_sizes, int n_in,
                              void* d_out, int out_size)
{
    const float* x     = (const float*)d_in[0];
    const int*   km    = (const int*)  d_in[1];
    const float* gamma = (const float*)d_in[2];
    const float* beta  = (const float*)d_in[3];
    float*       out   = (float*)d_out;

    cudaFuncSetAttribute(attn_kernel,
                         cudaFuncAttributeMaxDynamicSharedMemorySize, SMEM_TOTAL);

    prep_kernel<<<dim3(B_, 16), 256>>>(x);
    colsum_reduce_kernel<<<B_, 256>>>();
    attn_kernel<<<dim3(NTILE, B_), 128, SMEM_TOTAL>>>(km, gamma, beta);
    finalize_kernel<<<B_, 256>>>(out);
}